// round 16
// baseline (speedup 1.0000x reference)
#include <cuda_runtime.h>
#include <cuda_fp16.h>
#include <math.h>
#include <stdint.h>

#define N_NODES 50000
#define N_EDGES 1600000
#define IN_F    512
#define NH      128
#define NC      40
#define SCAN_B  ((N_NODES + 255) / 256)   // 196 blocks

// ---------------- static scratch (no runtime allocation) ----------------
__device__ int      g_deg_out_i[N_NODES];
__device__ int      g_deg_in_i [N_NODES];
__device__ int      g_cursor   [N_NODES];
__device__ int      g_row_ptr  [N_NODES + 1];
__device__ int      g_bsum     [256];
__device__ int2     g_edge     [N_EDGES];           // (src, half2(ns,ns) bits) by dst
__device__ float    g_ns       [N_NODES];
__device__ float    g_nd       [N_NODES];
__device__ uint16_t g_w1t_hi   [NH * IN_F];         // W1^T fp16 hi, [n][k]
__device__ uint32_t g_w2h      [NH * (NC / 2)];     // W2 as half2 pairs, [k][c2]
__device__ __half   g_h1       [(size_t)N_NODES * NH]; // X@W1 (unscaled, fp16)
__device__ __half   g_h2h      [(size_t)N_NODES * NC]; // x2@W2 (unscaled, fp16)

// ---------------- small helpers ----------------
__device__ __forceinline__ uint32_t smem_to_u32(const void* p) {
    uint32_t a;
    asm("{ .reg .u64 t; cvta.to.shared.u64 t, %1; cvt.u32.u64 %0, t; }" : "=r"(a) : "l"(p));
    return a;
}
__device__ __forceinline__ void ldmx4(uint32_t* r, uint32_t addr) {
    asm volatile("ldmatrix.sync.aligned.m8n8.x4.shared.b16 {%0,%1,%2,%3}, [%4];"
                 : "=r"(r[0]), "=r"(r[1]), "=r"(r[2]), "=r"(r[3]) : "r"(addr));
}
__device__ __forceinline__ void mma_f16(float* d, const uint32_t* a, const uint32_t* b) {
    asm volatile(
        "mma.sync.aligned.m16n8k16.row.col.f32.f16.f16.f32 "
        "{%0,%1,%2,%3}, {%4,%5,%6,%7}, {%8,%9}, {%0,%1,%2,%3};"
        : "+f"(d[0]), "+f"(d[1]), "+f"(d[2]), "+f"(d[3])
        : "r"(a[0]), "r"(a[1]), "r"(a[2]), "r"(a[3]), "r"(b[0]), "r"(b[1]));
}
__device__ __forceinline__ __half2 u2h2(uint32_t u) {
    __half2 h; memcpy(&h, &u, 4); return h;
}
__device__ __forceinline__ uint32_t h22u(__half2 h) {
    uint32_t u; memcpy(&u, &h, 4); return u;
}

// ---------------- zero counters each call ----------------
__global__ void zero_kernel() {
    int i = blockIdx.x * blockDim.x + threadIdx.x;
    int stride = gridDim.x * blockDim.x;
    for (int j = i; j < N_NODES; j += stride) {
        g_deg_out_i[j] = 0;
        g_deg_in_i [j] = 0;
        g_cursor   [j] = 0;
    }
}

__global__ void deg_kernel(const int* __restrict__ src, const int* __restrict__ dst) {
    int e = blockIdx.x * blockDim.x + threadIdx.x;
    if (e < N_EDGES) {
        atomicAdd(&g_deg_out_i[src[e]], 1);
        atomicAdd(&g_deg_in_i [dst[e]], 1);
    }
}

// ---------------- scan1 + norm fused ----------------
__global__ __launch_bounds__(256) void scan1norm_kernel() {
    __shared__ int s[256];
    int i = blockIdx.x * 256 + threadIdx.x;
    int di = (i < N_NODES) ? g_deg_in_i[i] : 0;
    if (i < N_NODES) {
        g_ns[i] = rsqrtf(fmaxf((float)g_deg_out_i[i], 1.f));
        g_nd[i] = rsqrtf(fmaxf((float)di, 1.f));
    }
    s[threadIdx.x] = di;
    __syncthreads();
    for (int off = 128; off > 0; off >>= 1) {
        if (threadIdx.x < off) s[threadIdx.x] += s[threadIdx.x + off];
        __syncthreads();
    }
    if (threadIdx.x == 0) g_bsum[blockIdx.x] = s[0];
}

// ---------------- scan2 + scan3 fused ----------------
__global__ __launch_bounds__(256) void scan23_kernel() {
    __shared__ int s[256];
    int t = threadIdx.x;
    int v = (t < SCAN_B) ? g_bsum[t] : 0;
    s[t] = v;
    __syncthreads();
    for (int off = 1; off < 256; off <<= 1) {
        int u = (t >= off) ? s[t - off] : 0;
        __syncthreads();
        s[t] += u;
        __syncthreads();
    }
    int myoff = (blockIdx.x > 0) ? s[blockIdx.x - 1] : 0;
    __syncthreads();
    int i = blockIdx.x * 256 + t;
    int d = (i < N_NODES) ? g_deg_in_i[i] : 0;
    s[t] = d;
    __syncthreads();
    for (int off = 1; off < 256; off <<= 1) {
        int u = (t >= off) ? s[t - off] : 0;
        __syncthreads();
        s[t] += u;
        __syncthreads();
    }
    if (i < N_NODES) g_row_ptr[i] = myoff + s[t] - d;
    if (blockIdx.x == 0 && t == 0) g_row_ptr[N_NODES] = N_EDGES;
}

// ---------------- fill: pack ns[src] as duplicated half2 -------------------
__global__ void fill_kernel(const int* __restrict__ src, const int* __restrict__ dst) {
    int e = blockIdx.x * blockDim.x + threadIdx.x;
    if (e < N_EDGES) {
        int d = dst[e];
        int s = src[e];
        int pos = g_row_ptr[d] + atomicAdd(&g_cursor[d], 1);
        __half h = __float2half_rn(g_ns[s]);
        __half2 hh = __half2half2(h);
        g_edge[pos] = make_int2(s, (int)h22u(hh));
    }
}

// ---------------- W1 -> transposed fp16; W2 -> half2 pairs -----------------
__global__ void w1split_kernel(const float* __restrict__ W1,
                               const float* __restrict__ W2) {
    int i = blockIdx.x * 256 + threadIdx.x;
    if (i < IN_F * NH) {
        int k = i >> 7, n = i & 127;
        __half hh = __float2half_rn(W1[i]);
        g_w1t_hi[n * IN_F + k] = __half_as_ushort(hh);
    }
    if (i < NH * (NC / 2)) {
        int k = i / (NC / 2), c2 = i % (NC / 2);
        __half2 p = __floats2half2_rn(W2[k * NC + c2 * 2], W2[k * NC + c2 * 2 + 1]);
        g_w2h[i] = h22u(p);
    }
}

// ---------------- GEMM1: h1 = X @ W1 via mma.sync fp16 2-term A-split ------
#define G1M_STAGE 24576
#define G1M_SMEM  (2 * G1M_STAGE)

__global__ __launch_bounds__(256) void gemm1_mma_kernel(const float* __restrict__ X) {
    extern __shared__ char smem[];
    const uint32_t sb = smem_to_u32(smem);
    const int tid  = threadIdx.x;
    const int lane = tid & 31;
    const int wid  = tid >> 5;
    const int bm   = blockIdx.x * 128;
    const int mw   = (wid & 3) * 32;
    const int nw   = (wid >> 2) * 64;

    float acc[2][8][4];
    #pragma unroll
    for (int i = 0; i < 2; i++)
        #pragma unroll
        for (int j = 0; j < 8; j++)
            #pragma unroll
            for (int q = 0; q < 4; q++) acc[i][j][q] = 0.f;

    const int lrow  = tid >> 1;
    const int lhalf = tid & 1;
    const int lsw   = (lrow >> 1) & 3;

    auto load_stage = [&](int st, int k0) {
        char* stg = smem + st * G1M_STAGE;
        {
            const int gr = bm + lrow;
            const bool ok = gr < N_NODES;
            const float* xp = &X[(size_t)gr * IN_F + k0 + lhalf * 16];
            #pragma unroll
            for (int q = 0; q < 4; q++) {
                float4 v = ok ? *reinterpret_cast<const float4*>(xp + q * 4)
                              : make_float4(0.f, 0.f, 0.f, 0.f);
                __half2 ha = __floats2half2_rn(v.x, v.y);
                __half2 hb = __floats2half2_rn(v.z, v.w);
                float2 haf = __half22float2(ha);
                float2 hbf = __half22float2(hb);
                __half2 la = __floats2half2_rn(v.x - haf.x, v.y - haf.y);
                __half2 lb = __floats2half2_rn(v.z - hbf.x, v.w - hbf.y);
                int c16 = lhalf * 2 + (q >> 1);
                uint32_t off = (uint32_t)(lrow * 64 + ((c16 ^ lsw) * 16) + (q & 1) * 8);
                *reinterpret_cast<uint2*>(stg + off)        = make_uint2(h22u(ha), h22u(hb));
                *reinterpret_cast<uint2*>(stg + 8192 + off) = make_uint2(h22u(la), h22u(lb));
            }
        }
        {
            const uint16_t* bh = &g_w1t_hi[lrow * IN_F + k0 + lhalf * 16];
            #pragma unroll
            for (int q = 0; q < 2; q++) {
                uint4 hv = *reinterpret_cast<const uint4*>(bh + q * 8);
                int c16 = lhalf * 2 + q;
                uint32_t off = (uint32_t)(lrow * 64 + ((c16 ^ lsw) * 16));
                *reinterpret_cast<uint4*>(stg + 16384 + off) = hv;
            }
        }
    };

    load_stage(0, 0);
    __syncthreads();

    const int a_rlane = lane & 15;
    const int a_kg    = lane >> 4;
    const int b_grp   = lane >> 3;
    const int b_rlane = (b_grp >> 1) * 8 + (lane & 7);
    const int b_kg    = b_grp & 1;

    const int NCHUNK = IN_F / 32;           // 16
    for (int c = 0; c < NCHUNK; c++) {
        const int cur = c & 1;
        if (c + 1 < NCHUNK) load_stage(cur ^ 1, (c + 1) * 32);

        const uint32_t sbase = sb + cur * G1M_STAGE;
        #pragma unroll
        for (int ks = 0; ks < 2; ks++) {
            uint32_t Ahi[2][4], Alo[2][4];
            #pragma unroll
            for (int mt = 0; mt < 2; mt++) {
                int row = mw + mt * 16 + a_rlane;
                uint32_t byteoff = (uint32_t)(row * 64 +
                    (((ks * 2 + a_kg) ^ ((row >> 1) & 3)) * 16));
                ldmx4(Ahi[mt], sbase + byteoff);
                ldmx4(Alo[mt], sbase + 8192 + byteoff);
            }
            uint32_t Bhi[8][2];
            #pragma unroll
            for (int ntp = 0; ntp < 4; ntp++) {
                int n = nw + ntp * 16 + b_rlane;
                uint32_t byteoff = (uint32_t)(n * 64 +
                    (((ks * 2 + b_kg) ^ ((n >> 1) & 3)) * 16));
                uint32_t rh[4];
                ldmx4(rh, sbase + 16384 + byteoff);
                Bhi[ntp * 2][0] = rh[0]; Bhi[ntp * 2][1] = rh[1];
                Bhi[ntp * 2 + 1][0] = rh[2]; Bhi[ntp * 2 + 1][1] = rh[3];
            }
            #pragma unroll
            for (int mt = 0; mt < 2; mt++)
                #pragma unroll
                for (int nt = 0; nt < 8; nt++)
                    mma_f16(acc[mt][nt], Ahi[mt], Bhi[nt]);
            #pragma unroll
            for (int mt = 0; mt < 2; mt++)
                #pragma unroll
                for (int nt = 0; nt < 8; nt++)
                    mma_f16(acc[mt][nt], Alo[mt], Bhi[nt]);
        }
        __syncthreads();
    }

    #pragma unroll
    for (int mt = 0; mt < 2; mt++) {
        int row = bm + mw + mt * 16 + (lane >> 2);
        #pragma unroll
        for (int nt = 0; nt < 8; nt++) {
            int col = nw + nt * 8 + (lane & 3) * 2;
            __half2 p0 = __floats2half2_rn(acc[mt][nt][0], acc[mt][nt][1]);
            __half2 p1 = __floats2half2_rn(acc[mt][nt][2], acc[mt][nt][3]);
            if (row < N_NODES)
                *reinterpret_cast<__half2*>(&g_h1[(size_t)row * NH + col]) = p0;
            if (row + 8 < N_NODES)
                *reinterpret_cast<__half2*>(&g_h1[(size_t)(row + 8) * NH + col]) = p1;
        }
    }
}

// ---------------- agg1 + gemm2 fused: HFMA2 w/ fp32 flush every <=8 adds ---
#define A1G2_BLOCKS 3125

__global__ __launch_bounds__(256) void agg1g2_kernel(const float* __restrict__ b1) {
    __shared__ uint32_t W2s[NH * (NC / 2)];      // 10KB, half2 pairs [k][c2]
    for (int i = threadIdx.x; i < NH * (NC / 2); i += 256) W2s[i] = g_w2h[i];
    __syncthreads();

    const int lane   = threadIdx.x & 31;
    const int half   = lane >> 4;
    const int li     = lane & 15;
    const int warp_g = (blockIdx.x * 256 + threadIdx.x) >> 5;
    const int nwarps = A1G2_BLOCKS * 8;

    for (int w = warp_g; w < N_NODES; w += nwarps) {
        int beg = g_row_ptr[w], end = g_row_ptr[w + 1];

        float2 s0 = make_float2(0.f, 0.f), s1 = s0, s2 = s0, s3 = s0;
        for (int j = beg; j < end; j += 32) {
            int n = end - j; if (n > 32) n = 32;
            int2 ed = (j + lane < end) ? g_edge[j + lane] : make_int2(0, 0);
            // two sub-blocks of 16 edges; flush to fp32 between (<=8 adds/acc)
            #pragma unroll
            for (int sub = 0; sub < 2; sub++) {
                int i0 = sub * 16;
                if (i0 >= n) break;
                __half2 a0 = u2h2(0), a1 = u2h2(0), a2 = u2h2(0), a3 = u2h2(0);
                int lim = n < i0 + 16 ? n : i0 + 16;
                #pragma unroll 8
                for (int i = i0; i < lim; i += 2) {
                    int e = i + half;
                    int      s  = __shfl_sync(0xffffffffu, ed.x, e & 31);
                    uint32_t pf = (uint32_t)__shfl_sync(0xffffffffu, ed.y, e & 31);
                    if (e >= n) { pf = 0u; s = 0; }
                    uint4 v = __ldg(reinterpret_cast<const uint4*>(&g_h1[(size_t)s * NH]) + li);
                    __half2 f2 = u2h2(pf);
                    a0 = __hfma2(f2, u2h2(v.x), a0);
                    a1 = __hfma2(f2, u2h2(v.y), a1);
                    a2 = __hfma2(f2, u2h2(v.z), a2);
                    a3 = __hfma2(f2, u2h2(v.w), a3);
                }
                float2 f0 = __half22float2(a0);
                float2 f1 = __half22float2(a1);
                float2 f2v = __half22float2(a2);
                float2 f3 = __half22float2(a3);
                s0.x += f0.x; s0.y += f0.y;
                s1.x += f1.x; s1.y += f1.y;
                s2.x += f2v.x; s2.y += f2v.y;
                s3.x += f3.x; s3.y += f3.y;
            }
        }
        // combine halves in fp32
        s0.x += __shfl_xor_sync(0xffffffffu, s0.x, 16);
        s0.y += __shfl_xor_sync(0xffffffffu, s0.y, 16);
        s1.x += __shfl_xor_sync(0xffffffffu, s1.x, 16);
        s1.y += __shfl_xor_sync(0xffffffffu, s1.y, 16);
        s2.x += __shfl_xor_sync(0xffffffffu, s2.x, 16);
        s2.y += __shfl_xor_sync(0xffffffffu, s2.y, 16);
        s3.x += __shfl_xor_sync(0xffffffffu, s3.x, 16);
        s3.y += __shfl_xor_sync(0xffffffffu, s3.y, 16);

        float nd = g_nd[w];
        int fb = li * 8;
        float4 bA = __ldg(reinterpret_cast<const float4*>(b1 + fb));
        float4 bB = __ldg(reinterpret_cast<const float4*>(b1 + fb + 4));
        float x0 = fmaxf(s0.x * nd + bA.x, 0.f);
        float x1 = fmaxf(s0.y * nd + bA.y, 0.f);
        float x2 = fmaxf(s1.x * nd + bA.z, 0.f);
        float x3 = fmaxf(s1.y * nd + bA.w, 0.f);
        float x4 = fmaxf(s2.x * nd + bB.x, 0.f);
        float x5 = fmaxf(s2.y * nd + bB.y, 0.f);
        float x6 = fmaxf(s3.x * nd + bB.z, 0.f);
        float x7 = fmaxf(s3.y * nd + bB.w, 0.f);

        // pack x2 feats: xu[q] = (x_{fb+2q}, x_{fb+2q+1}) as half2
        uint32_t xu[4];
        xu[0] = h22u(__floats2half2_rn(x0, x1));
        xu[1] = h22u(__floats2half2_rn(x2, x3));
        xu[2] = h22u(__floats2half2_rn(x4, x5));
        xu[3] = h22u(__floats2half2_rn(x6, x7));

        // matvec: lane c<20 computes h2 cols (2c, 2c+1); fp32 flush per 8 k
        float2 ms = make_float2(0.f, 0.f);
        const int c = lane;
        const bool act = c < (NC / 2);
        #pragma unroll
        for (int kc = 0; kc < NH; kc += 8) {         // 16 chunks of 8 k
            __half2 macc = u2h2(0);
            #pragma unroll
            for (int k = kc; k < kc + 8; k += 2) {
                int sl = k >> 3;
                int q  = (k >> 1) & 3;
                uint32_t pr = __shfl_sync(0xffffffffu, xu[q], sl);
                __half2 ph = u2h2(pr);
                if (act) {
                    __half2 xk0 = __half2half2(__low2half(ph));
                    __half2 xk1 = __half2half2(__high2half(ph));
                    macc = __hfma2(xk0, u2h2(W2s[k * (NC / 2) + c]), macc);
                    macc = __hfma2(xk1, u2h2(W2s[(k + 1) * (NC / 2) + c]), macc);
                }
            }
            if (act) {
                float2 f = __half22float2(macc);
                ms.x += f.x; ms.y += f.y;
            }
        }
        if (act)
            *reinterpret_cast<__half2*>(&g_h2h[(size_t)w * NC + c * 2]) =
                __floats2half2_rn(ms.x, ms.y);
    }
}

// ---------------- agg2: HFMA2 w/ fp32 flush every 8 edges ------------------
__global__ void agg2_kernel(const float* __restrict__ b2, float* __restrict__ out) {
    int t = blockIdx.x * blockDim.x + threadIdx.x;
    int w = t >> 5, lane = t & 31;
    if (w >= N_NODES) return;
    int beg = g_row_ptr[w], end = g_row_ptr[w + 1];

    float2 sacc = make_float2(0.f, 0.f);
    const bool act = lane < (NC / 2);
    for (int j = beg; j < end; j += 32) {
        int n = end - j; if (n > 32) n = 32;
        int2 ed = (j + lane < end) ? g_edge[j + lane] : make_int2(0, 0);
        #pragma unroll
        for (int i0 = 0; i0 < 32; i0 += 8) {
            if (i0 >= n) break;
            __half2 acc = u2h2(0);
            int lim = n < i0 + 8 ? n : i0 + 8;
            #pragma unroll 8
            for (int i = i0; i < lim; i++) {
                int      s  = __shfl_sync(0xffffffffu, ed.x, i);
                uint32_t pf = (uint32_t)__shfl_sync(0xffffffffu, ed.y, i);
                if (act) {
                    uint32_t v = __ldg(reinterpret_cast<const uint32_t*>(
                        &g_h2h[(size_t)s * NC]) + lane);
                    acc = __hfma2(u2h2(pf), u2h2(v), acc);
                }
            }
            if (act) {
                float2 f = __half22float2(acc);
                sacc.x += f.x; sacc.y += f.y;
            }
        }
    }
    if (act) {
        float nd = g_nd[w];
        float2 bb = __ldg(reinterpret_cast<const float2*>(b2) + lane);
        *reinterpret_cast<float2*>(&out[(size_t)w * NC + lane * 2]) =
            make_float2(sacc.x * nd + bb.x, sacc.y * nd + bb.y);
    }
}

// ---------------- launch ----------------
extern "C" void kernel_launch(void* const* d_in, const int* in_sizes, int n_in,
                              void* d_out, int out_size) {
    const float* X   = (const float*)d_in[0];
    const float* W1  = (const float*)d_in[1];
    const float* b1  = (const float*)d_in[2];
    const float* W2  = (const float*)d_in[3];
    const float* b2  = (const float*)d_in[4];
    const int*   src = (const int*)  d_in[5];
    const int*   dst = (const int*)  d_in[6];
    float* out = (float*)d_out;

    static cudaStream_t s_side = nullptr;
    static cudaEvent_t  ev_fork = nullptr, ev_join = nullptr;
    if (s_side == nullptr) {
        cudaStreamCreateWithFlags(&s_side, cudaStreamNonBlocking);
        cudaEventCreateWithFlags(&ev_fork, cudaEventDisableTiming);
        cudaEventCreateWithFlags(&ev_join, cudaEventDisableTiming);
        cudaFuncSetAttribute(gemm1_mma_kernel,
                             cudaFuncAttributeMaxDynamicSharedMemorySize, G1M_SMEM);
    }

    // fork: side stream runs the graph-prep chain
    cudaEventRecord(ev_fork, 0);
    cudaStreamWaitEvent(s_side, ev_fork, 0);

    zero_kernel<<<256, 256, 0, s_side>>>();
    deg_kernel<<<(N_EDGES + 255) / 256, 256, 0, s_side>>>(src, dst);
    scan1norm_kernel<<<SCAN_B, 256, 0, s_side>>>();
    scan23_kernel<<<SCAN_B, 256, 0, s_side>>>();
    fill_kernel<<<(N_EDGES + 255) / 256, 256, 0, s_side>>>(src, dst);

    // main stream: weight conversions + tensor-core GEMM1
    w1split_kernel<<<(IN_F * NH + 255) / 256, 256>>>(W1, W2);
    gemm1_mma_kernel<<<(N_NODES + 127) / 128, 256, G1M_SMEM>>>(X);

    // join
    cudaEventRecord(ev_join, s_side);
    cudaStreamWaitEvent(0, ev_join, 0);

    // fused agg1+gemm2, then agg2
    agg1g2_kernel<<<A1G2_BLOCKS, 256>>>(b1);
    agg2_kernel<<<(N_NODES * 32 + 255) / 256, 256>>>(b2, out);
}

// round 17
// speedup vs baseline: 1.0170x; 1.0170x over previous
#include <cuda_runtime.h>
#include <cuda_fp16.h>
#include <math.h>
#include <stdint.h>

#define N_NODES 50000
#define N_EDGES 1600000
#define IN_F    512
#define NH      128
#define NC      40
#define SCAN_B  ((N_NODES + 255) / 256)   // 196 blocks

// ---------------- static scratch (no runtime allocation) ----------------
__device__ int      g_deg_out_i[N_NODES];
__device__ int      g_deg_in_i [N_NODES];
__device__ int      g_cursor   [N_NODES];
__device__ int      g_row_ptr  [N_NODES + 1];
__device__ int      g_bsum     [256];
__device__ int2     g_edge     [N_EDGES];           // (src, half2(ns,ns) bits) by dst
__device__ float    g_ns       [N_NODES];
__device__ float    g_nd       [N_NODES];
__device__ uint16_t g_w1t_hi   [NH * IN_F];         // W1^T fp16 hi, [n][k]
__device__ uint32_t g_w2h      [NH * (NC / 2)];     // W2 as half2 pairs, [k][c2]
__device__ __half   g_h1       [(size_t)N_NODES * NH]; // X@W1 (unscaled, fp16)
__device__ __half   g_h2h      [(size_t)N_NODES * NC]; // x2@W2 (unscaled, fp16)

// ---------------- small helpers ----------------
__device__ __forceinline__ uint32_t smem_to_u32(const void* p) {
    uint32_t a;
    asm("{ .reg .u64 t; cvta.to.shared.u64 t, %1; cvt.u32.u64 %0, t; }" : "=r"(a) : "l"(p));
    return a;
}
__device__ __forceinline__ void ldmx4(uint32_t* r, uint32_t addr) {
    asm volatile("ldmatrix.sync.aligned.m8n8.x4.shared.b16 {%0,%1,%2,%3}, [%4];"
                 : "=r"(r[0]), "=r"(r[1]), "=r"(r[2]), "=r"(r[3]) : "r"(addr));
}
__device__ __forceinline__ void mma_f16(float* d, const uint32_t* a, const uint32_t* b) {
    asm volatile(
        "mma.sync.aligned.m16n8k16.row.col.f32.f16.f16.f32 "
        "{%0,%1,%2,%3}, {%4,%5,%6,%7}, {%8,%9}, {%0,%1,%2,%3};"
        : "+f"(d[0]), "+f"(d[1]), "+f"(d[2]), "+f"(d[3])
        : "r"(a[0]), "r"(a[1]), "r"(a[2]), "r"(a[3]), "r"(b[0]), "r"(b[1]));
}
__device__ __forceinline__ __half2 u2h2(uint32_t u) {
    __half2 h; memcpy(&h, &u, 4); return h;
}
__device__ __forceinline__ uint32_t h22u(__half2 h) {
    uint32_t u; memcpy(&u, &h, 4); return u;
}

// ---------------- zero counters each call ----------------
__global__ void zero_kernel() {
    int i = blockIdx.x * blockDim.x + threadIdx.x;
    int stride = gridDim.x * blockDim.x;
    for (int j = i; j < N_NODES; j += stride) {
        g_deg_out_i[j] = 0;
        g_deg_in_i [j] = 0;
        g_cursor   [j] = 0;
    }
}

__global__ void deg_kernel(const int* __restrict__ src, const int* __restrict__ dst) {
    int e = blockIdx.x * blockDim.x + threadIdx.x;
    if (e < N_EDGES) {
        atomicAdd(&g_deg_out_i[src[e]], 1);
        atomicAdd(&g_deg_in_i [dst[e]], 1);
    }
}

// ---------------- scan1 + norm fused ----------------
__global__ __launch_bounds__(256) void scan1norm_kernel() {
    __shared__ int s[256];
    int i = blockIdx.x * 256 + threadIdx.x;
    int di = (i < N_NODES) ? g_deg_in_i[i] : 0;
    if (i < N_NODES) {
        g_ns[i] = rsqrtf(fmaxf((float)g_deg_out_i[i], 1.f));
        g_nd[i] = rsqrtf(fmaxf((float)di, 1.f));
    }
    s[threadIdx.x] = di;
    __syncthreads();
    for (int off = 128; off > 0; off >>= 1) {
        if (threadIdx.x < off) s[threadIdx.x] += s[threadIdx.x + off];
        __syncthreads();
    }
    if (threadIdx.x == 0) g_bsum[blockIdx.x] = s[0];
}

// ---------------- scan2 + scan3 fused ----------------
__global__ __launch_bounds__(256) void scan23_kernel() {
    __shared__ int s[256];
    int t = threadIdx.x;
    int v = (t < SCAN_B) ? g_bsum[t] : 0;
    s[t] = v;
    __syncthreads();
    for (int off = 1; off < 256; off <<= 1) {
        int u = (t >= off) ? s[t - off] : 0;
        __syncthreads();
        s[t] += u;
        __syncthreads();
    }
    int myoff = (blockIdx.x > 0) ? s[blockIdx.x - 1] : 0;
    __syncthreads();
    int i = blockIdx.x * 256 + t;
    int d = (i < N_NODES) ? g_deg_in_i[i] : 0;
    s[t] = d;
    __syncthreads();
    for (int off = 1; off < 256; off <<= 1) {
        int u = (t >= off) ? s[t - off] : 0;
        __syncthreads();
        s[t] += u;
        __syncthreads();
    }
    if (i < N_NODES) g_row_ptr[i] = myoff + s[t] - d;
    if (blockIdx.x == 0 && t == 0) g_row_ptr[N_NODES] = N_EDGES;
}

// ---------------- fill: pack ns[src] as duplicated half2 -------------------
__global__ void fill_kernel(const int* __restrict__ src, const int* __restrict__ dst) {
    int e = blockIdx.x * blockDim.x + threadIdx.x;
    if (e < N_EDGES) {
        int d = dst[e];
        int s = src[e];
        int pos = g_row_ptr[d] + atomicAdd(&g_cursor[d], 1);
        __half h = __float2half_rn(g_ns[s]);
        __half2 hh = __half2half2(h);
        g_edge[pos] = make_int2(s, (int)h22u(hh));
    }
}

// ---------------- W1 -> transposed fp16; W2 -> half2 pairs -----------------
__global__ void w1split_kernel(const float* __restrict__ W1,
                               const float* __restrict__ W2) {
    int i = blockIdx.x * 256 + threadIdx.x;
    if (i < IN_F * NH) {
        int k = i >> 7, n = i & 127;
        __half hh = __float2half_rn(W1[i]);
        g_w1t_hi[n * IN_F + k] = __half_as_ushort(hh);
    }
    if (i < NH * (NC / 2)) {
        int k = i / (NC / 2), c2 = i % (NC / 2);
        __half2 p = __floats2half2_rn(W2[k * NC + c2 * 2], W2[k * NC + c2 * 2 + 1]);
        g_w2h[i] = h22u(p);
    }
}

// ---------------- GEMM1: h1 = X @ W1 via mma.sync fp16 2-term A-split ------
#define G1M_STAGE 24576
#define G1M_SMEM  (2 * G1M_STAGE)

__global__ __launch_bounds__(256) void gemm1_mma_kernel(const float* __restrict__ X) {
    extern __shared__ char smem[];
    const uint32_t sb = smem_to_u32(smem);
    const int tid  = threadIdx.x;
    const int lane = tid & 31;
    const int wid  = tid >> 5;
    const int bm   = blockIdx.x * 128;
    const int mw   = (wid & 3) * 32;
    const int nw   = (wid >> 2) * 64;

    float acc[2][8][4];
    #pragma unroll
    for (int i = 0; i < 2; i++)
        #pragma unroll
        for (int j = 0; j < 8; j++)
            #pragma unroll
            for (int q = 0; q < 4; q++) acc[i][j][q] = 0.f;

    const int lrow  = tid >> 1;
    const int lhalf = tid & 1;
    const int lsw   = (lrow >> 1) & 3;

    auto load_stage = [&](int st, int k0) {
        char* stg = smem + st * G1M_STAGE;
        {
            const int gr = bm + lrow;
            const bool ok = gr < N_NODES;
            const float* xp = &X[(size_t)gr * IN_F + k0 + lhalf * 16];
            #pragma unroll
            for (int q = 0; q < 4; q++) {
                float4 v = ok ? *reinterpret_cast<const float4*>(xp + q * 4)
                              : make_float4(0.f, 0.f, 0.f, 0.f);
                __half2 ha = __floats2half2_rn(v.x, v.y);
                __half2 hb = __floats2half2_rn(v.z, v.w);
                float2 haf = __half22float2(ha);
                float2 hbf = __half22float2(hb);
                __half2 la = __floats2half2_rn(v.x - haf.x, v.y - haf.y);
                __half2 lb = __floats2half2_rn(v.z - hbf.x, v.w - hbf.y);
                int c16 = lhalf * 2 + (q >> 1);
                uint32_t off = (uint32_t)(lrow * 64 + ((c16 ^ lsw) * 16) + (q & 1) * 8);
                *reinterpret_cast<uint2*>(stg + off)        = make_uint2(h22u(ha), h22u(hb));
                *reinterpret_cast<uint2*>(stg + 8192 + off) = make_uint2(h22u(la), h22u(lb));
            }
        }
        {
            const uint16_t* bh = &g_w1t_hi[lrow * IN_F + k0 + lhalf * 16];
            #pragma unroll
            for (int q = 0; q < 2; q++) {
                uint4 hv = *reinterpret_cast<const uint4*>(bh + q * 8);
                int c16 = lhalf * 2 + q;
                uint32_t off = (uint32_t)(lrow * 64 + ((c16 ^ lsw) * 16));
                *reinterpret_cast<uint4*>(stg + 16384 + off) = hv;
            }
        }
    };

    load_stage(0, 0);
    __syncthreads();

    const int a_rlane = lane & 15;
    const int a_kg    = lane >> 4;
    const int b_grp   = lane >> 3;
    const int b_rlane = (b_grp >> 1) * 8 + (lane & 7);
    const int b_kg    = b_grp & 1;

    const int NCHUNK = IN_F / 32;           // 16
    for (int c = 0; c < NCHUNK; c++) {
        const int cur = c & 1;
        if (c + 1 < NCHUNK) load_stage(cur ^ 1, (c + 1) * 32);

        const uint32_t sbase = sb + cur * G1M_STAGE;
        #pragma unroll
        for (int ks = 0; ks < 2; ks++) {
            uint32_t Ahi[2][4], Alo[2][4];
            #pragma unroll
            for (int mt = 0; mt < 2; mt++) {
                int row = mw + mt * 16 + a_rlane;
                uint32_t byteoff = (uint32_t)(row * 64 +
                    (((ks * 2 + a_kg) ^ ((row >> 1) & 3)) * 16));
                ldmx4(Ahi[mt], sbase + byteoff);
                ldmx4(Alo[mt], sbase + 8192 + byteoff);
            }
            uint32_t Bhi[8][2];
            #pragma unroll
            for (int ntp = 0; ntp < 4; ntp++) {
                int n = nw + ntp * 16 + b_rlane;
                uint32_t byteoff = (uint32_t)(n * 64 +
                    (((ks * 2 + b_kg) ^ ((n >> 1) & 3)) * 16));
                uint32_t rh[4];
                ldmx4(rh, sbase + 16384 + byteoff);
                Bhi[ntp * 2][0] = rh[0]; Bhi[ntp * 2][1] = rh[1];
                Bhi[ntp * 2 + 1][0] = rh[2]; Bhi[ntp * 2 + 1][1] = rh[3];
            }
            #pragma unroll
            for (int mt = 0; mt < 2; mt++)
                #pragma unroll
                for (int nt = 0; nt < 8; nt++)
                    mma_f16(acc[mt][nt], Ahi[mt], Bhi[nt]);
            #pragma unroll
            for (int mt = 0; mt < 2; mt++)
                #pragma unroll
                for (int nt = 0; nt < 8; nt++)
                    mma_f16(acc[mt][nt], Alo[mt], Bhi[nt]);
        }
        __syncthreads();
    }

    #pragma unroll
    for (int mt = 0; mt < 2; mt++) {
        int row = bm + mw + mt * 16 + (lane >> 2);
        #pragma unroll
        for (int nt = 0; nt < 8; nt++) {
            int col = nw + nt * 8 + (lane & 3) * 2;
            __half2 p0 = __floats2half2_rn(acc[mt][nt][0], acc[mt][nt][1]);
            __half2 p1 = __floats2half2_rn(acc[mt][nt][2], acc[mt][nt][3]);
            if (row < N_NODES)
                *reinterpret_cast<__half2*>(&g_h1[(size_t)row * NH + col]) = p0;
            if (row + 8 < N_NODES)
                *reinterpret_cast<__half2*>(&g_h1[(size_t)(row + 8) * NH + col]) = p1;
        }
    }
}

// ---------------- agg1 + gemm2 fused: batched loads (MLP 16) + flush<=8 ----
#define A1G2_BLOCKS 3125

__global__ __launch_bounds__(256) void agg1g2_kernel(const float* __restrict__ b1) {
    __shared__ uint32_t W2s[NH * (NC / 2)];      // 10KB, half2 pairs [k][c2]
    for (int i = threadIdx.x; i < NH * (NC / 2); i += 256) W2s[i] = g_w2h[i];
    __syncthreads();

    const int lane   = threadIdx.x & 31;
    const int half   = lane >> 4;
    const int li     = lane & 15;
    const int warp_g = (blockIdx.x * 256 + threadIdx.x) >> 5;
    const int nwarps = A1G2_BLOCKS * 8;

    for (int w = warp_g; w < N_NODES; w += nwarps) {
        int beg = g_row_ptr[w], end = g_row_ptr[w + 1];

        float2 s0 = make_float2(0.f, 0.f), s1 = s0, s2 = s0, s3 = s0;

        int j = beg;
        // ---- fast path: full 32-edge blocks, all 16 pair-loads in flight ----
        for (; j + 32 <= end; j += 32) {
            int2 ed = g_edge[j + lane];
            uint4 v[16];
            #pragma unroll
            for (int p = 0; p < 16; p++) {
                int s = __shfl_sync(0xffffffffu, ed.x, 2 * p + half);
                v[p] = __ldg(reinterpret_cast<const uint4*>(&g_h1[(size_t)s * NH]) + li);
            }
            #pragma unroll
            for (int sub = 0; sub < 2; sub++) {
                __half2 a0 = u2h2(0), a1 = u2h2(0), a2 = u2h2(0), a3 = u2h2(0);
                #pragma unroll
                for (int p = sub * 8; p < sub * 8 + 8; p++) {
                    uint32_t pf = (uint32_t)__shfl_sync(0xffffffffu, ed.y, 2 * p + half);
                    __half2 f2 = u2h2(pf);
                    a0 = __hfma2(f2, u2h2(v[p].x), a0);
                    a1 = __hfma2(f2, u2h2(v[p].y), a1);
                    a2 = __hfma2(f2, u2h2(v[p].z), a2);
                    a3 = __hfma2(f2, u2h2(v[p].w), a3);
                }
                float2 f0 = __half22float2(a0);
                float2 f1 = __half22float2(a1);
                float2 f2v = __half22float2(a2);
                float2 f3 = __half22float2(a3);
                s0.x += f0.x; s0.y += f0.y;
                s1.x += f1.x; s1.y += f1.y;
                s2.x += f2v.x; s2.y += f2v.y;
                s3.x += f3.x; s3.y += f3.y;
            }
        }
        // ---- tail: guarded (n < 32) ----
        if (j < end) {
            int n = end - j;
            int2 ed = (j + lane < end) ? g_edge[j + lane] : make_int2(0, 0);
            #pragma unroll
            for (int sub = 0; sub < 2; sub++) {
                int i0 = sub * 16;
                if (i0 >= n) break;
                __half2 a0 = u2h2(0), a1 = u2h2(0), a2 = u2h2(0), a3 = u2h2(0);
                int lim = n < i0 + 16 ? n : i0 + 16;
                #pragma unroll 8
                for (int i = i0; i < lim; i += 2) {
                    int e = i + half;
                    int      s  = __shfl_sync(0xffffffffu, ed.x, e & 31);
                    uint32_t pf = (uint32_t)__shfl_sync(0xffffffffu, ed.y, e & 31);
                    if (e >= n) { pf = 0u; s = 0; }
                    uint4 vv = __ldg(reinterpret_cast<const uint4*>(&g_h1[(size_t)s * NH]) + li);
                    __half2 f2 = u2h2(pf);
                    a0 = __hfma2(f2, u2h2(vv.x), a0);
                    a1 = __hfma2(f2, u2h2(vv.y), a1);
                    a2 = __hfma2(f2, u2h2(vv.z), a2);
                    a3 = __hfma2(f2, u2h2(vv.w), a3);
                }
                float2 f0 = __half22float2(a0);
                float2 f1 = __half22float2(a1);
                float2 f2v = __half22float2(a2);
                float2 f3 = __half22float2(a3);
                s0.x += f0.x; s0.y += f0.y;
                s1.x += f1.x; s1.y += f1.y;
                s2.x += f2v.x; s2.y += f2v.y;
                s3.x += f3.x; s3.y += f3.y;
            }
        }

        // combine halves in fp32
        s0.x += __shfl_xor_sync(0xffffffffu, s0.x, 16);
        s0.y += __shfl_xor_sync(0xffffffffu, s0.y, 16);
        s1.x += __shfl_xor_sync(0xffffffffu, s1.x, 16);
        s1.y += __shfl_xor_sync(0xffffffffu, s1.y, 16);
        s2.x += __shfl_xor_sync(0xffffffffu, s2.x, 16);
        s2.y += __shfl_xor_sync(0xffffffffu, s2.y, 16);
        s3.x += __shfl_xor_sync(0xffffffffu, s3.x, 16);
        s3.y += __shfl_xor_sync(0xffffffffu, s3.y, 16);

        float nd = g_nd[w];
        int fb = li * 8;
        float4 bA = __ldg(reinterpret_cast<const float4*>(b1 + fb));
        float4 bB = __ldg(reinterpret_cast<const float4*>(b1 + fb + 4));
        float x0 = fmaxf(s0.x * nd + bA.x, 0.f);
        float x1 = fmaxf(s0.y * nd + bA.y, 0.f);
        float x2 = fmaxf(s1.x * nd + bA.z, 0.f);
        float x3 = fmaxf(s1.y * nd + bA.w, 0.f);
        float x4 = fmaxf(s2.x * nd + bB.x, 0.f);
        float x5 = fmaxf(s2.y * nd + bB.y, 0.f);
        float x6 = fmaxf(s3.x * nd + bB.z, 0.f);
        float x7 = fmaxf(s3.y * nd + bB.w, 0.f);

        uint32_t xu[4];
        xu[0] = h22u(__floats2half2_rn(x0, x1));
        xu[1] = h22u(__floats2half2_rn(x2, x3));
        xu[2] = h22u(__floats2half2_rn(x4, x5));
        xu[3] = h22u(__floats2half2_rn(x6, x7));

        // matvec: lane c<20 computes h2 cols (2c, 2c+1); fp32 flush per 8 k
        float2 ms = make_float2(0.f, 0.f);
        const int c = lane;
        const bool act = c < (NC / 2);
        #pragma unroll
        for (int kc = 0; kc < NH; kc += 8) {
            __half2 macc = u2h2(0);
            #pragma unroll
            for (int k = kc; k < kc + 8; k += 2) {
                int sl = k >> 3;
                int q  = (k >> 1) & 3;
                uint32_t pr = __shfl_sync(0xffffffffu, xu[q], sl);
                __half2 ph = u2h2(pr);
                if (act) {
                    __half2 xk0 = __half2half2(__low2half(ph));
                    __half2 xk1 = __half2half2(__high2half(ph));
                    macc = __hfma2(xk0, u2h2(W2s[k * (NC / 2) + c]), macc);
                    macc = __hfma2(xk1, u2h2(W2s[(k + 1) * (NC / 2) + c]), macc);
                }
            }
            if (act) {
                float2 f = __half22float2(macc);
                ms.x += f.x; ms.y += f.y;
            }
        }
        if (act)
            *reinterpret_cast<__half2*>(&g_h2h[(size_t)w * NC + c * 2]) =
                __floats2half2_rn(ms.x, ms.y);
    }
}

// ---------------- agg2: batched loads (MLP 16) + fp32 flush every 8 --------
__global__ void agg2_kernel(const float* __restrict__ b2, float* __restrict__ out) {
    int t = blockIdx.x * blockDim.x + threadIdx.x;
    int w = t >> 5, lane = t & 31;
    if (w >= N_NODES) return;
    int beg = g_row_ptr[w], end = g_row_ptr[w + 1];

    float2 sacc = make_float2(0.f, 0.f);
    const bool act = lane < (NC / 2);

    int j = beg;
    // fast path: full 32-edge blocks, 16 loads in flight per half
    for (; j + 32 <= end; j += 32) {
        int2 ed = g_edge[j + lane];
        #pragma unroll
        for (int sub = 0; sub < 2; sub++) {
            uint32_t vv[16];
            #pragma unroll
            for (int i = 0; i < 16; i++) {
                int s = __shfl_sync(0xffffffffu, ed.x, sub * 16 + i);
                if (act)
                    vv[i] = __ldg(reinterpret_cast<const uint32_t*>(
                        &g_h2h[(size_t)s * NC]) + lane);
            }
            #pragma unroll
            for (int g = 0; g < 2; g++) {
                __half2 acc = u2h2(0);
                #pragma unroll
                for (int i = g * 8; i < g * 8 + 8; i++) {
                    uint32_t pf = (uint32_t)__shfl_sync(0xffffffffu, ed.y, sub * 16 + i);
                    if (act) acc = __hfma2(u2h2(pf), u2h2(vv[i]), acc);
                }
                if (act) {
                    float2 f = __half22float2(acc);
                    sacc.x += f.x; sacc.y += f.y;
                }
            }
        }
    }
    // tail: guarded
    if (j < end) {
        int n = end - j;
        int2 ed = (j + lane < end) ? g_edge[j + lane] : make_int2(0, 0);
        #pragma unroll
        for (int i0 = 0; i0 < 32; i0 += 8) {
            if (i0 >= n) break;
            __half2 acc = u2h2(0);
            int lim = n < i0 + 8 ? n : i0 + 8;
            #pragma unroll 8
            for (int i = i0; i < lim; i++) {
                int      s  = __shfl_sync(0xffffffffu, ed.x, i);
                uint32_t pf = (uint32_t)__shfl_sync(0xffffffffu, ed.y, i);
                if (act) {
                    uint32_t v = __ldg(reinterpret_cast<const uint32_t*>(
                        &g_h2h[(size_t)s * NC]) + lane);
                    acc = __hfma2(u2h2(pf), u2h2(v), acc);
                }
            }
            if (act) {
                float2 f = __half22float2(acc);
                sacc.x += f.x; sacc.y += f.y;
            }
        }
    }

    if (act) {
        float nd = g_nd[w];
        float2 bb = __ldg(reinterpret_cast<const float2*>(b2) + lane);
        *reinterpret_cast<float2*>(&out[(size_t)w * NC + lane * 2]) =
            make_float2(sacc.x * nd + bb.x, sacc.y * nd + bb.y);
    }
}

// ---------------- launch ----------------
extern "C" void kernel_launch(void* const* d_in, const int* in_sizes, int n_in,
                              void* d_out, int out_size) {
    const float* X   = (const float*)d_in[0];
    const float* W1  = (const float*)d_in[1];
    const float* b1  = (const float*)d_in[2];
    const float* W2  = (const float*)d_in[3];
    const float* b2  = (const float*)d_in[4];
    const int*   src = (const int*)  d_in[5];
    const int*   dst = (const int*)  d_in[6];
    float* out = (float*)d_out;

    static cudaStream_t s_side = nullptr;
    static cudaEvent_t  ev_fork = nullptr, ev_join = nullptr;
    if (s_side == nullptr) {
        cudaStreamCreateWithFlags(&s_side, cudaStreamNonBlocking);
        cudaEventCreateWithFlags(&ev_fork, cudaEventDisableTiming);
        cudaEventCreateWithFlags(&ev_join, cudaEventDisableTiming);
        cudaFuncSetAttribute(gemm1_mma_kernel,
                             cudaFuncAttributeMaxDynamicSharedMemorySize, G1M_SMEM);
    }

    // fork: side stream runs the graph-prep chain
    cudaEventRecord(ev_fork, 0);
    cudaStreamWaitEvent(s_side, ev_fork, 0);

    zero_kernel<<<256, 256, 0, s_side>>>();
    deg_kernel<<<(N_EDGES + 255) / 256, 256, 0, s_side>>>(src, dst);
    scan1norm_kernel<<<SCAN_B, 256, 0, s_side>>>();
    scan23_kernel<<<SCAN_B, 256, 0, s_side>>>();
    fill_kernel<<<(N_EDGES + 255) / 256, 256, 0, s_side>>>(src, dst);

    // main stream: weight conversions + tensor-core GEMM1
    w1split_kernel<<<(IN_F * NH + 255) / 256, 256>>>(W1, W2);
    gemm1_mma_kernel<<<(N_NODES + 127) / 128, 256, G1M_SMEM>>>(X);

    // join
    cudaEventRecord(ev_join, s_side);
    cudaStreamWaitEvent(0, ev_join, 0);

    // fused agg1+gemm2, then agg2
    agg1g2_kernel<<<A1G2_BLOCKS, 256>>>(b1);
    agg2_kernel<<<(N_NODES * 32 + 255) / 256, 256>>>(b2, out);
}